// round 6
// baseline (speedup 1.0000x reference)
#include <cuda_runtime.h>
#include <cuda_fp16.h>
#include <math.h>
#include <stdint.h>

#define BB   2
#define TT   2048
#define EE   1024
#define HQn  16
#define HKVn 4
#define DD   64
#define GG   4

#define ROWS (BB*TT)
#define KVW  (HKVn*DD)
#define Y_ELEMS  ((size_t)BB*TT*EE)
#define ATT_ELEMS ((size_t)BB*HQn*TT*TT)
#define ZHEADS (BB*HQn)          // 32
#define NQB    (TT/128)          // 16

typedef __half h16;

// ---------------- device scratch ----------------
__device__ float g_Q[ROWS * EE];
__device__ float g_K[ROWS * KVW];
__device__ float g_V[ROWS * KVW];
__device__ float g_Att[ATT_ELEMS];                    // fallback if out lacks att

__device__ h16 g_xh[ROWS * EE],  g_xl[ROWS * EE];
__device__ h16 g_Qh[ROWS * EE],  g_Ql[ROWS * EE];
__device__ h16 g_Kh[ROWS * KVW], g_Kl[ROWS * KVW];
__device__ h16 g_Vth[BB * KVW * TT];                  // [(b*4+hkv)*64+d][t]
__device__ h16 g_Yh[ROWS * EE],  g_Yl[ROWS * EE];
__device__ h16 g_Wqth[EE * EE];
__device__ h16 g_Wkth[EE * KVW];
__device__ h16 g_Wvth[EE * KVW];
__device__ h16 g_Woth[EE * EE];

__device__ h16 g_Ph[ATT_ELEMS];                       // exp(S) hi
__device__ h16 g_Pl[ATT_ELEMS];                       // exp(S) lo
__device__ float g_PS[ZHEADS * NQB * TT];             // partial row sums [z][kb][row]

// ---------------- helpers ----------------
__device__ __forceinline__ void hsplit(float x, h16& h, h16& l)
{
    h = __float2half_rn(x);
    l = __float2half_rn(x - __half2float(h));
}

__device__ __forceinline__ void mma_f16(float (&c)[4],
                                        uint32_t a0, uint32_t a1,
                                        uint32_t a2, uint32_t a3,
                                        uint32_t b0, uint32_t b1)
{
    asm volatile(
        "mma.sync.aligned.m16n8k16.row.col.f32.f16.f16.f32 "
        "{%0,%1,%2,%3}, {%4,%5,%6,%7}, {%8,%9}, {%0,%1,%2,%3};"
        : "+f"(c[0]), "+f"(c[1]), "+f"(c[2]), "+f"(c[3])
        : "r"(a0), "r"(a1), "r"(a2), "r"(a3), "r"(b0), "r"(b1));
}

// ---------------- preprocessing ----------------
__global__ __launch_bounds__(256) void wtrans_half(
    const float* __restrict__ W, h16* __restrict__ Wth, int K, int N)
{
    __shared__ float s[32][33];
    const int c0 = blockIdx.x * 32;
    const int r0 = blockIdx.y * 32;
    const int tx = threadIdx.x, ty = threadIdx.y;
    for (int i = ty; i < 32; i += 8)
        s[i][tx] = W[(size_t)(r0 + i) * N + c0 + tx];
    __syncthreads();
    for (int i = ty; i < 32; i += 8)
        Wth[(size_t)(c0 + i) * K + r0 + tx] = __float2half_rn(s[tx][i]);
}

__global__ __launch_bounds__(256) void vtrans_half(
    const float* __restrict__ V, h16* __restrict__ Vth)
{
    __shared__ float s[32][33];
    const int c0 = blockIdx.x * 32;
    const int r0 = blockIdx.y * 32;
    const int b  = r0 >> 11;
    const int t0 = r0 & 2047;
    const int tx = threadIdx.x, ty = threadIdx.y;
    for (int i = ty; i < 32; i += 8)
        s[i][tx] = V[(size_t)(r0 + i) * KVW + c0 + tx];
    __syncthreads();
    for (int i = ty; i < 32; i += 8)
        Vth[(size_t)(b * KVW + c0 + i) * TT + t0 + tx] = __float2half_rn(s[tx][i]);
}

__global__ __launch_bounds__(256) void split_x(
    const float4* __restrict__ src, h16* __restrict__ hi, h16* __restrict__ lo, int n4)
{
    int i = blockIdx.x * 256 + threadIdx.x;
    if (i >= n4) return;
    float4 v = src[i];
    h16 hx, lx, hy, ly, hz, lz, hw, lw;
    hsplit(v.x, hx, lx); hsplit(v.y, hy, ly);
    hsplit(v.z, hz, lz); hsplit(v.w, hw, lw);
    __half2 a, b2;
    a.x = hx; a.y = hy; b2.x = hz; b2.y = hw;
    ((__half2*)hi)[2 * i] = a; ((__half2*)hi)[2 * i + 1] = b2;
    a.x = lx; a.y = ly; b2.x = lz; b2.y = lw;
    ((__half2*)lo)[2 * i] = a; ((__half2*)lo)[2 * i + 1] = b2;
}

// ---------------- GEMM 2-pass fp16 ----------------
__device__ __forceinline__ void gemm2p_body(
    const h16* __restrict__ Ah, const h16* __restrict__ Al,
    const h16* __restrict__ Bth, const float* __restrict__ bias,
    float* __restrict__ C, int M, int N, int K)
{
    __shared__ h16 sAh[128][24], sAl[128][24], sBh[128][24];

    const int tid  = threadIdx.x;
    const int w    = tid >> 5, lane = tid & 31;
    const int lg   = lane >> 2, tg = lane & 3;
    const int m0   = (w & 1) * 64;
    const int n0   = (w >> 1) * 32;
    const int blkM = blockIdx.y * 128;
    const int blkN = blockIdx.x * 128;

    const int lrow = tid >> 1;
    const int lk   = (tid & 1) * 8;

    float acc[4][4][4];
#pragma unroll
    for (int i = 0; i < 4; i++)
#pragma unroll
        for (int j = 0; j < 4; j++)
#pragma unroll
            for (int v = 0; v < 4; v++) acc[i][j][v] = 0.f;

    const h16* pAh = Ah  + (size_t)(blkM + lrow) * K + lk;
    const h16* pAl = Al  + (size_t)(blkM + lrow) * K + lk;
    const h16* pBh = Bth + (size_t)(blkN + lrow) * K + lk;

    uint4 rAh = *(const uint4*)pAh;
    uint4 rAl = *(const uint4*)pAl;
    uint4 rBh = *(const uint4*)pBh;

    const int niter = K / 16;
    for (int it = 0; it < niter; it++) {
        *(uint4*)&sAh[lrow][lk] = rAh;
        *(uint4*)&sAl[lrow][lk] = rAl;
        *(uint4*)&sBh[lrow][lk] = rBh;
        __syncthreads();

        if (it + 1 < niter) {
            rAh = *(const uint4*)(pAh + (it + 1) * 16);
            rAl = *(const uint4*)(pAl + (it + 1) * 16);
            rBh = *(const uint4*)(pBh + (it + 1) * 16);
        }

        uint32_t ah[4][4], al[4][4], bh[4][2];
#pragma unroll
        for (int mt = 0; mt < 4; mt++) {
            const int r = m0 + mt * 16 + lg;
            ah[mt][0] = *(const uint32_t*)&sAh[r][tg * 2];
            ah[mt][1] = *(const uint32_t*)&sAh[r + 8][tg * 2];
            ah[mt][2] = *(const uint32_t*)&sAh[r][tg * 2 + 8];
            ah[mt][3] = *(const uint32_t*)&sAh[r + 8][tg * 2 + 8];
            al[mt][0] = *(const uint32_t*)&sAl[r][tg * 2];
            al[mt][1] = *(const uint32_t*)&sAl[r + 8][tg * 2];
            al[mt][2] = *(const uint32_t*)&sAl[r][tg * 2 + 8];
            al[mt][3] = *(const uint32_t*)&sAl[r + 8][tg * 2 + 8];
        }
#pragma unroll
        for (int nt = 0; nt < 4; nt++) {
            const int n = n0 + nt * 8 + lg;
            bh[nt][0] = *(const uint32_t*)&sBh[n][tg * 2];
            bh[nt][1] = *(const uint32_t*)&sBh[n][tg * 2 + 8];
        }
#pragma unroll
        for (int mt = 0; mt < 4; mt++)
#pragma unroll
            for (int nt = 0; nt < 4; nt++) {
                mma_f16(acc[mt][nt], ah[mt][0], ah[mt][1], ah[mt][2], ah[mt][3],
                        bh[nt][0], bh[nt][1]);
                mma_f16(acc[mt][nt], al[mt][0], al[mt][1], al[mt][2], al[mt][3],
                        bh[nt][0], bh[nt][1]);
            }
        __syncthreads();
    }

#pragma unroll
    for (int mt = 0; mt < 4; mt++)
#pragma unroll
        for (int nt = 0; nt < 4; nt++) {
            const int col = blkN + n0 + nt * 8 + 2 * tg;
            const float b0 = bias[col], b1 = bias[col + 1];
            const int r0 = blkM + m0 + mt * 16 + lg;
            float2 o;
            o.x = acc[mt][nt][0] + b0; o.y = acc[mt][nt][1] + b1;
            *(float2*)(C + (size_t)r0 * N + col) = o;
            o.x = acc[mt][nt][2] + b0; o.y = acc[mt][nt][3] + b1;
            *(float2*)(C + (size_t)(r0 + 8) * N + col) = o;
        }
}

__global__ __launch_bounds__(256) void gemm2p(
    const h16* __restrict__ Ah, const h16* __restrict__ Al,
    const h16* __restrict__ Bth, const float* __restrict__ bias,
    float* __restrict__ C, int M, int N, int K)
{
    gemm2p_body(Ah, Al, Bth, bias, C, M, N, K);
}

__global__ __launch_bounds__(256) void gemm2p_kv(
    const h16* __restrict__ Ah, const h16* __restrict__ Al,
    const h16* __restrict__ Wkth, const float* __restrict__ bk, float* __restrict__ Kout,
    const h16* __restrict__ Wvth, const float* __restrict__ bv, float* __restrict__ Vout)
{
    if (blockIdx.z == 0) gemm2p_body(Ah, Al, Wkth, bk, Kout, ROWS, KVW, EE);
    else                 gemm2p_body(Ah, Al, Wvth, bv, Vout, ROWS, KVW, EE);
}

// ---------------- RoPE + split ----------------
__global__ __launch_bounds__(256) void rope_split(
    const float* __restrict__ buf, h16* __restrict__ hi,
    h16* __restrict__ lo, int nheads)
{
    int idx = blockIdx.x * 256 + threadIdx.x;
    int ii  = idx & 31;
    int h   = (idx >> 5) % nheads;
    int row = idx / (32 * nheads);
    int t   = row & (TT - 1);
    float ang = (float)(t + 1) * exp2f((float)ii * (-13.2877123795494f / 32.0f));
    float sn, cs;
    sincosf(ang, &sn, &cs);
    size_t off = (size_t)row * (nheads * 64) + h * 64 + ii;
    float x0 = buf[off], x1 = buf[off + 32];
    float y0 = x0 * cs - x1 * sn;
    float y1 = x1 * cs + x0 * sn;
    h16 h0, l0, h1, l1;
    hsplit(y0, h0, l0);
    hsplit(y1, h1, l1);
    hi[off] = h0; hi[off + 32] = h1;
    lo[off] = l0; lo[off + 32] = l1;
}

// ---------------- scores: P~ = exp(QK^T/8), masked, + partial row sums ----
__global__ __launch_bounds__(256) void attn_scores_exp(
    const h16* __restrict__ Qh, const h16* __restrict__ Ql,
    const h16* __restrict__ Kh,
    h16* __restrict__ Ph, h16* __restrict__ Pl, float* __restrict__ PS)
{
    int idx = blockIdx.x;
    int qb = (int)((sqrtf(8.f * idx + 1.f) - 1.f) * 0.5f);
    while ((qb + 1) * (qb + 2) / 2 <= idx) qb++;
    while (qb * (qb + 1) / 2 > idx) qb--;
    const int kb = idx - qb * (qb + 1) / 2;

    const int z   = blockIdx.y;
    const int b   = z >> 4;
    const int g   = (z >> 2) & 3;
    const int hkv = z & 3;
    const int hq  = hkv * GG + g;

    extern __shared__ h16 sm[];
    h16 (*sQh)[72] = (h16(*)[72])sm;
    h16 (*sQl)[72] = (h16(*)[72])(sm + 128 * 72);
    h16 (*sKh)[72] = (h16(*)[72])(sm + 2 * 128 * 72);

    const int tid  = threadIdx.x;
    const int w    = tid >> 5, lane = tid & 31;
    const int lg   = lane >> 2, tg = lane & 3;
    const int m0   = (w & 1) * 64;
    const int n0   = (w >> 1) * 32;

    {
        const int lrow = tid >> 1;
        const int lc   = (tid & 1) * 32;
        const h16* qh = Qh + (size_t)(b * TT + qb * 128 + lrow) * EE + hq * 64 + lc;
        const h16* ql = Ql + (size_t)(b * TT + qb * 128 + lrow) * EE + hq * 64 + lc;
        const h16* kh = Kh + (size_t)(b * TT + kb * 128 + lrow) * KVW + hkv * 64 + lc;
#pragma unroll
        for (int v = 0; v < 4; v++) {
            *(uint4*)&sQh[lrow][lc + v * 8] = *(const uint4*)(qh + v * 8);
            *(uint4*)&sQl[lrow][lc + v * 8] = *(const uint4*)(ql + v * 8);
            *(uint4*)&sKh[lrow][lc + v * 8] = *(const uint4*)(kh + v * 8);
        }
    }
    __syncthreads();

    float acc[4][4][4];
#pragma unroll
    for (int i = 0; i < 4; i++)
#pragma unroll
        for (int j = 0; j < 4; j++)
#pragma unroll
            for (int v = 0; v < 4; v++) acc[i][j][v] = 0.f;

#pragma unroll
    for (int kk = 0; kk < 64; kk += 16) {
        uint32_t ah[4][4], al[4][4], bh[4][2];
#pragma unroll
        for (int mt = 0; mt < 4; mt++) {
            const int r = m0 + mt * 16 + lg;
            ah[mt][0] = *(const uint32_t*)&sQh[r][kk + tg * 2];
            ah[mt][1] = *(const uint32_t*)&sQh[r + 8][kk + tg * 2];
            ah[mt][2] = *(const uint32_t*)&sQh[r][kk + tg * 2 + 8];
            ah[mt][3] = *(const uint32_t*)&sQh[r + 8][kk + tg * 2 + 8];
            al[mt][0] = *(const uint32_t*)&sQl[r][kk + tg * 2];
            al[mt][1] = *(const uint32_t*)&sQl[r + 8][kk + tg * 2];
            al[mt][2] = *(const uint32_t*)&sQl[r][kk + tg * 2 + 8];
            al[mt][3] = *(const uint32_t*)&sQl[r + 8][kk + tg * 2 + 8];
        }
#pragma unroll
        for (int nt = 0; nt < 4; nt++) {
            const int n = n0 + nt * 8 + lg;
            bh[nt][0] = *(const uint32_t*)&sKh[n][kk + tg * 2];
            bh[nt][1] = *(const uint32_t*)&sKh[n][kk + tg * 2 + 8];
        }
#pragma unroll
        for (int mt = 0; mt < 4; mt++)
#pragma unroll
            for (int nt = 0; nt < 4; nt++) {
                mma_f16(acc[mt][nt], ah[mt][0], ah[mt][1], ah[mt][2], ah[mt][3],
                        bh[nt][0], bh[nt][1]);
                mma_f16(acc[mt][nt], al[mt][0], al[mt][1], al[mt][2], al[mt][3],
                        bh[nt][0], bh[nt][1]);
            }
    }

    // epilogue: exp, mask (diag tiles), split-store, partial row sums
    __syncthreads();
    float* srow = (float*)sm;   // reuse smem: 128 floats
    if (tid < 128) srow[tid] = 0.f;
    __syncthreads();

    h16* phb = Ph + ((size_t)z * TT + qb * 128) * TT + kb * 128;
    h16* plb = Pl + ((size_t)z * TT + qb * 128) * TT + kb * 128;
    const bool diag = (kb == qb);

#pragma unroll
    for (int mt = 0; mt < 4; mt++) {
        const int r0 = m0 + mt * 16 + lg;
        float s0 = 0.f, s1 = 0.f;
#pragma unroll
        for (int nt = 0; nt < 4; nt++) {
            const int col = n0 + nt * 8 + 2 * tg;
            float p0 = __expf(acc[mt][nt][0] * 0.125f);
            float p1 = __expf(acc[mt][nt][1] * 0.125f);
            float p2 = __expf(acc[mt][nt][2] * 0.125f);
            float p3 = __expf(acc[mt][nt][3] * 0.125f);
            if (diag) {
                if (col > r0)      p0 = 0.f;
                if (col + 1 > r0)  p1 = 0.f;
                if (col > r0 + 8)     p2 = 0.f;
                if (col + 1 > r0 + 8) p3 = 0.f;
            }
            s0 += p0 + p1;
            s1 += p2 + p3;
            h16 h0, l0, h1, l1;
            __half2 t;
            hsplit(p0, h0, l0); hsplit(p1, h1, l1);
            t.x = h0; t.y = h1; *(__half2*)&phb[(size_t)r0 * TT + col] = t;
            t.x = l0; t.y = l1; *(__half2*)&plb[(size_t)r0 * TT + col] = t;
            hsplit(p2, h0, l0); hsplit(p3, h1, l1);
            t.x = h0; t.y = h1; *(__half2*)&phb[(size_t)(r0 + 8) * TT + col] = t;
            t.x = l0; t.y = l1; *(__half2*)&plb[(size_t)(r0 + 8) * TT + col] = t;
        }
        // reduce across the quad (tg lanes)
        s0 += __shfl_xor_sync(0xffffffffu, s0, 1);
        s0 += __shfl_xor_sync(0xffffffffu, s0, 2);
        s1 += __shfl_xor_sync(0xffffffffu, s1, 1);
        s1 += __shfl_xor_sync(0xffffffffu, s1, 2);
        if (tg == 0) {
            atomicAdd(&srow[r0], s0);
            atomicAdd(&srow[r0 + 8], s1);
        }
    }
    __syncthreads();
    if (tid < 128)
        PS[((size_t)z * NQB + kb) * TT + qb * 128 + tid] = srow[tid];
}

// ---------------- PV: normalize, write att_weights, Y = P @ V -------------
__global__ __launch_bounds__(256) void attn_pv_norm(
    const h16* __restrict__ Ph, const h16* __restrict__ Pl,
    const float* __restrict__ PS, const h16* __restrict__ Vth,
    float* __restrict__ attw, h16* __restrict__ Yh, h16* __restrict__ Yl)
{
    const int qb = (gridDim.x - 1) - blockIdx.x;   // heavy first
    const int z  = blockIdx.y;
    const int b   = z >> 4;
    const int g   = (z >> 2) & 3;
    const int hkv = z & 3;

    extern __shared__ h16 sm[];
    h16 (*sPh)[72] = (h16(*)[72])sm;
    h16 (*sPl)[72] = (h16(*)[72])(sm + 128 * 72);
    h16 (*sVh)[72] = (h16(*)[72])(sm + 2 * 128 * 72);
    float* sInv    = (float*)(sm + (2 * 128 + 64) * 72);

    const int tid  = threadIdx.x;
    const int w    = tid >> 5, lane = tid & 31;
    const int lg   = lane >> 2, tg = lane & 3;
    const int m0   = (w & 3) * 32;
    const int n0   = (w >> 2) * 32;

    // per-row inverse sums (deterministic: serial sum over kb partials)
    if (tid < 128) {
        float s = 0.f;
        for (int k2 = 0; k2 <= qb; k2++)
            s += PS[((size_t)z * NQB + k2) * TT + qb * 128 + tid];
        sInv[tid] = 1.0f / s;
    }
    __syncthreads();

    const int prow = tid >> 1;
    const int pc   = (tid & 1) * 32;
    const int vrow = tid >> 2;
    const int vc   = (tid & 3) * 16;

    float acc[2][4][4];
#pragma unroll
    for (int i = 0; i < 2; i++)
#pragma unroll
        for (int j = 0; j < 4; j++)
#pragma unroll
            for (int v = 0; v < 4; v++) acc[i][j][v] = 0.f;

    const h16* phsrc = Ph + ((size_t)z * TT + qb * 128 + prow) * TT + pc;
    const h16* plsrc = Pl + ((size_t)z * TT + qb * 128 + prow) * TT + pc;
    float*     pout  = attw + ((size_t)z * TT + qb * 128 + prow) * TT + pc;
    const float myinv = sInv[prow];
    const h16* vbh = Vth + (size_t)(b * KVW + hkv * 64 + vrow) * TT + vc;

    const int nkb = 2 * qb + 2;
    for (int kb = 0; kb < nkb; kb++) {
#pragma unroll
        for (int v = 0; v < 4; v++) {
            uint4 hv = *(const uint4*)(phsrc + kb * 64 + v * 8);
            uint4 lv = *(const uint4*)(plsrc + kb * 64 + v * 8);
            *(uint4*)&sPh[prow][pc + v * 8] = hv;
            *(uint4*)&sPl[prow][pc + v * 8] = lv;
            const __half2* hh = (const __half2*)&hv;
            const __half2* ll = (const __half2*)&lv;
            float4 o0, o1;
            o0.x = (__low2float(hh[0]) + __low2float(ll[0])) * myinv;
            o0.y = (__high2float(hh[0]) + __high2float(ll[0])) * myinv;
            o0.z = (__low2float(hh[1]) + __low2float(ll[1])) * myinv;
            o0.w = (__high2float(hh[1]) + __high2float(ll[1])) * myinv;
            o1.x = (__low2float(hh[2]) + __low2float(ll[2])) * myinv;
            o1.y = (__high2float(hh[2]) + __high2float(ll[2])) * myinv;
            o1.z = (__low2float(hh[3]) + __low2float(ll[3])) * myinv;
            o1.w = (__high2float(hh[3]) + __high2float(ll[3])) * myinv;
            *(float4*)(pout + kb * 64 + v * 8)     = o0;
            *(float4*)(pout + kb * 64 + v * 8 + 4) = o1;
        }
        *(uint4*)&sVh[vrow][vc]     = *(const uint4*)(vbh + kb * 64);
        *(uint4*)&sVh[vrow][vc + 8] = *(const uint4*)(vbh + kb * 64 + 8);
        __syncthreads();

#pragma unroll
        for (int kk = 0; kk < 64; kk += 16) {
            uint32_t ah[2][4], al[2][4], bh[4][2];
#pragma unroll
            for (int mt = 0; mt < 2; mt++) {
                const int r = m0 + mt * 16 + lg;
                ah[mt][0] = *(const uint32_t*)&sPh[r][kk + tg * 2];
                ah[mt][1] = *(const uint32_t*)&sPh[r + 8][kk + tg * 2];
                ah[mt][2] = *(const uint32_t*)&sPh[r][kk + tg * 2 + 8];
                ah[mt][3] = *(const uint32_t*)&sPh[r + 8][kk + tg * 2 + 8];
                al[mt][0] = *(const uint32_t*)&sPl[r][kk + tg * 2];
                al[mt][1] = *(const uint32_t*)&sPl[r + 8][kk + tg * 2];
                al[mt][2] = *(const uint32_t*)&sPl[r][kk + tg * 2 + 8];
                al[mt][3] = *(const uint32_t*)&sPl[r + 8][kk + tg * 2 + 8];
            }
#pragma unroll
            for (int nt = 0; nt < 4; nt++) {
                const int n = n0 + nt * 8 + lg;
                bh[nt][0] = *(const uint32_t*)&sVh[n][kk + tg * 2];
                bh[nt][1] = *(const uint32_t*)&sVh[n][kk + tg * 2 + 8];
            }
#pragma unroll
            for (int mt = 0; mt < 2; mt++)
#pragma unroll
                for (int nt = 0; nt < 4; nt++) {
                    mma_f16(acc[mt][nt], ah[mt][0], ah[mt][1], ah[mt][2], ah[mt][3],
                            bh[nt][0], bh[nt][1]);
                    mma_f16(acc[mt][nt], al[mt][0], al[mt][1], al[mt][2], al[mt][3],
                            bh[nt][0], bh[nt][1]);
                }
        }
        __syncthreads();
    }

    // zero-fill upper-triangle columns for these rows
    {
        const int zc0 = (qb + 1) * 128;
        const int zcols = TT - zc0;              // multiple of 128
        float4 zero = {0.f, 0.f, 0.f, 0.f};
        float* zbase = attw + ((size_t)z * TT + qb * 128) * TT + zc0;
        const int n4 = 128 * (zcols / 4);
        for (int i = tid; i < n4; i += 256) {
            const int rr = i / (zcols / 4);
            const int cc = (i - rr * (zcols / 4)) * 4;
            *(float4*)(zbase + (size_t)rr * TT + cc) = zero;
        }
    }

    const int colbase = hkv * 256 + g * 64;
#pragma unroll
    for (int mt = 0; mt < 2; mt++) {
        const int r = m0 + mt * 16 + lg;
        const float inv0 = sInv[r];
        const float inv1 = sInv[r + 8];
#pragma unroll
        for (int nt = 0; nt < 4; nt++) {
            const int col = colbase + n0 + nt * 8 + 2 * tg;
            const int r0 = b * TT + qb * 128 + m0 + mt * 16 + lg;
            h16 h0, l0, h1, l1;
            __half2 t;
            hsplit(acc[mt][nt][0] * inv0, h0, l0); hsplit(acc[mt][nt][1] * inv0, h1, l1);
            t.x = h0; t.y = h1; *(__half2*)&Yh[(size_t)r0 * EE + col] = t;
            t.x = l0; t.y = l1; *(__half2*)&Yl[(size_t)r0 * EE + col] = t;
            hsplit(acc[mt][nt][2] * inv1, h0, l0); hsplit(acc[mt][nt][3] * inv1, h1, l1);
            t.x = h0; t.y = h1; *(__half2*)&Yh[(size_t)(r0 + 8) * EE + col] = t;
            t.x = l0; t.y = l1; *(__half2*)&Yl[(size_t)(r0 + 8) * EE + col] = t;
        }
    }
}

// ---------------- launch ----------------
extern "C" void kernel_launch(void* const* d_in, const int* in_sizes, int n_in,
                              void* d_out, int out_size)
{
    const float* x  = (const float*)d_in[0];
    const float* Wq = (const float*)d_in[2];
    const float* bq = (const float*)d_in[3];
    const float* Wk = (const float*)d_in[4];
    const float* bk = (const float*)d_in[5];
    const float* Wv = (const float*)d_in[6];
    const float* bv = (const float*)d_in[7];
    const float* Wo = (const float*)d_in[8];
    const float* bo = (const float*)d_in[9];
    float* out = (float*)d_out;

    float *Qb, *Kb, *Vb, *attScratch, *PS;
    h16 *xh, *xl, *Qh, *Ql, *Kh, *Kl, *Vth, *Yh, *Yl, *Ph, *Pl;
    h16 *Wqth, *Wkth, *Wvth, *Woth;
    cudaGetSymbolAddress((void**)&Qb, g_Q);
    cudaGetSymbolAddress((void**)&Kb, g_K);
    cudaGetSymbolAddress((void**)&Vb, g_V);
    cudaGetSymbolAddress((void**)&attScratch, g_Att);
    cudaGetSymbolAddress((void**)&xh, g_xh);
    cudaGetSymbolAddress((void**)&xl, g_xl);
    cudaGetSymbolAddress((void**)&Qh, g_Qh);
    cudaGetSymbolAddress((void**)&Ql, g_Ql);
    cudaGetSymbolAddress((void**)&Kh, g_Kh);
    cudaGetSymbolAddress((void**)&Kl, g_Kl);
    cudaGetSymbolAddress((void**)&Vth, g_Vth);
    cudaGetSymbolAddress((void**)&Yh, g_Yh);
    cudaGetSymbolAddress((void**)&Yl, g_Yl);
    cudaGetSymbolAddress((void**)&Ph, g_Ph);
    cudaGetSymbolAddress((void**)&Pl, g_Pl);
    cudaGetSymbolAddress((void**)&PS, g_PS);
    cudaGetSymbolAddress((void**)&Wqth, g_Wqth);
    cudaGetSymbolAddress((void**)&Wkth, g_Wkth);
    cudaGetSymbolAddress((void**)&Wvth, g_Wvth);
    cudaGetSymbolAddress((void**)&Woth, g_Woth);

    float* att = ((size_t)out_size >= Y_ELEMS + ATT_ELEMS) ? (out + Y_ELEMS)
                                                           : attScratch;

    const int SMEM_SC = 3 * 128 * 72 * (int)sizeof(h16);                  // 55296
    const int SMEM_PV = (2 * 128 + 64) * 72 * (int)sizeof(h16) + 512;     // 46592
    cudaFuncSetAttribute(attn_scores_exp, cudaFuncAttributeMaxDynamicSharedMemorySize, SMEM_SC);
    cudaFuncSetAttribute(attn_pv_norm,   cudaFuncAttributeMaxDynamicSharedMemorySize, SMEM_PV);

    // 0) preprocessing
    wtrans_half<<<dim3(EE / 32, EE / 32),  dim3(32, 8)>>>(Wq, Wqth, EE, EE);
    wtrans_half<<<dim3(KVW / 32, EE / 32), dim3(32, 8)>>>(Wk, Wkth, EE, KVW);
    wtrans_half<<<dim3(KVW / 32, EE / 32), dim3(32, 8)>>>(Wv, Wvth, EE, KVW);
    wtrans_half<<<dim3(EE / 32, EE / 32),  dim3(32, 8)>>>(Wo, Woth, EE, EE);
    split_x<<<(ROWS * EE / 4 + 255) / 256, 256>>>((const float4*)x, xh, xl, ROWS * EE / 4);

    // 1) projections
    gemm2p<<<dim3(EE / 128, ROWS / 128), 256>>>(xh, xl, Wqth, bq, Qb, ROWS, EE, EE);
    gemm2p_kv<<<dim3(KVW / 128, ROWS / 128, 2), 256>>>(xh, xl, Wkth, bk, Kb, Wvth, bv, Vb);

    // 2) RoPE + split; V transpose+convert
    rope_split<<<(ROWS * HQn * 32) / 256, 256>>>(Qb, Qh, Ql, HQn);
    rope_split<<<(ROWS * HKVn * 32) / 256, 256>>>(Kb, Kh, Kl, HKVn);
    vtrans_half<<<dim3(KVW / 32, ROWS / 32), dim3(32, 8)>>>(Vb, Vth);

    // 3) scores + exp + partial sums (triangular grid)
    attn_scores_exp<<<dim3(NQB * (NQB + 1) / 2, ZHEADS), 256, SMEM_SC>>>(
        Qh, Ql, Kh, Ph, Pl, PS);

    // 4) PV: normalize + write att_weights + Y
    attn_pv_norm<<<dim3(NQB, ZHEADS), 256, SMEM_PV>>>(Ph, Pl, PS, Vth, att, Yh, Yl);

    // 5) output projection
    gemm2p<<<dim3(EE / 128, ROWS / 128), 256>>>(Yh, Yl, Woth, bo, out, ROWS, EE, EE);
}

// round 10
// speedup vs baseline: 1.1669x; 1.1669x over previous
#include <cuda_runtime.h>
#include <cuda_fp16.h>
#include <math.h>
#include <stdint.h>

#define BB   2
#define TT   2048
#define EE   1024
#define HQn  16
#define HKVn 4
#define DD   64
#define GG   4

#define ROWS (BB*TT)
#define KVW  (HKVn*DD)
#define Y_ELEMS  ((size_t)BB*TT*EE)
#define ATT_ELEMS ((size_t)BB*HQn*TT*TT)

typedef __half h16;

// ---------------- device scratch ----------------
__device__ float g_Q[ROWS * EE];
__device__ float g_K[ROWS * KVW];
__device__ float g_V[ROWS * KVW];
__device__ float g_Att[ATT_ELEMS];

__device__ h16 g_xh[ROWS * EE],  g_xl[ROWS * EE];
__device__ h16 g_Qh[ROWS * EE],  g_Ql[ROWS * EE];
__device__ h16 g_Kh[ROWS * KVW], g_Kl[ROWS * KVW];
__device__ h16 g_Vth[BB * KVW * TT];
__device__ h16 g_Yh[ROWS * EE],  g_Yl[ROWS * EE];
__device__ h16 g_Wqth[EE * EE];
__device__ h16 g_Wkth[EE * KVW];
__device__ h16 g_Wvth[EE * KVW];
__device__ h16 g_Woth[EE * EE];

// ---------------- helpers ----------------
__device__ __forceinline__ void hsplit(float x, h16& h, h16& l)
{
    h = __float2half_rn(x);
    l = __float2half_rn(x - __half2float(h));
}

__device__ __forceinline__ void mma_f16(float (&c)[4],
                                        uint32_t a0, uint32_t a1,
                                        uint32_t a2, uint32_t a3,
                                        uint32_t b0, uint32_t b1)
{
    asm volatile(
        "mma.sync.aligned.m16n8k16.row.col.f32.f16.f16.f32 "
        "{%0,%1,%2,%3}, {%4,%5,%6,%7}, {%8,%9}, {%0,%1,%2,%3};"
        : "+f"(c[0]), "+f"(c[1]), "+f"(c[2]), "+f"(c[3])
        : "r"(a0), "r"(a1), "r"(a2), "r"(a3), "r"(b0), "r"(b1));
}

__device__ __forceinline__ uint32_t smem_u32(const void* p)
{
    return (uint32_t)__cvta_generic_to_shared(p);
}

__device__ __forceinline__ void cp16(uint32_t dst, const void* src)
{
    asm volatile("cp.async.cg.shared.global [%0], [%1], 16;" :: "r"(dst), "l"(src));
}
#define CP_COMMIT() asm volatile("cp.async.commit_group;")
#define CP_WAIT1()  asm volatile("cp.async.wait_group 1;")

__device__ __forceinline__ void ldsm_x4(uint32_t& r0, uint32_t& r1,
                                        uint32_t& r2, uint32_t& r3, uint32_t a)
{
    asm volatile("ldmatrix.sync.aligned.m8n8.x4.shared.b16 {%0,%1,%2,%3}, [%4];"
        : "=r"(r0), "=r"(r1), "=r"(r2), "=r"(r3) : "r"(a));
}

// ---------------- preprocessing ----------------
// All four weights in one launch: W [K=1024][N] fp32 -> Wt [N][K] fp16
__global__ __launch_bounds__(256) void wtrans_all(
    const float* __restrict__ Wq, const float* __restrict__ Wk,
    const float* __restrict__ Wv, const float* __restrict__ Wo,
    h16* __restrict__ Dq, h16* __restrict__ Dk,
    h16* __restrict__ Dv, h16* __restrict__ Do)
{
    const int z = blockIdx.z;
    const float* W; h16* D; int N;
    if      (z == 0) { W = Wq; D = Dq; N = EE;  }
    else if (z == 1) { W = Wk; D = Dk; N = KVW; }
    else if (z == 2) { W = Wv; D = Dv; N = KVW; }
    else             { W = Wo; D = Do; N = EE;  }
    const int c0 = blockIdx.x * 32;
    if (c0 >= N) return;
    const int r0 = blockIdx.y * 32;

    __shared__ float s[32][33];
    const int tx = threadIdx.x, ty = threadIdx.y;
    for (int i = ty; i < 32; i += 8)
        s[i][tx] = W[(size_t)(r0 + i) * N + c0 + tx];
    __syncthreads();
    for (int i = ty; i < 32; i += 8)
        D[(size_t)(c0 + i) * EE + r0 + tx] = __float2half_rn(s[tx][i]);
}

__global__ __launch_bounds__(256) void vtrans_half(
    const float* __restrict__ V, h16* __restrict__ Vth)
{
    __shared__ float s[32][33];
    const int c0 = blockIdx.x * 32;
    const int r0 = blockIdx.y * 32;
    const int b  = r0 >> 11;
    const int t0 = r0 & 2047;
    const int tx = threadIdx.x, ty = threadIdx.y;
    for (int i = ty; i < 32; i += 8)
        s[i][tx] = V[(size_t)(r0 + i) * KVW + c0 + tx];
    __syncthreads();
    for (int i = ty; i < 32; i += 8)
        Vth[(size_t)(b * KVW + c0 + i) * TT + t0 + tx] = __float2half_rn(s[tx][i]);
}

__global__ __launch_bounds__(256) void split_x(
    const float4* __restrict__ src, h16* __restrict__ hi, h16* __restrict__ lo, int n4)
{
    int i = blockIdx.x * 256 + threadIdx.x;
    if (i >= n4) return;
    float4 v = src[i];
    h16 hx, lx, hy, ly, hz, lz, hw, lw;
    hsplit(v.x, hx, lx); hsplit(v.y, hy, ly);
    hsplit(v.z, hz, lz); hsplit(v.w, hw, lw);
    __half2 a, b2;
    a.x = hx; a.y = hy; b2.x = hz; b2.y = hw;
    ((__half2*)hi)[2 * i] = a; ((__half2*)hi)[2 * i + 1] = b2;
    a.x = lx; a.y = ly; b2.x = lz; b2.y = lw;
    ((__half2*)lo)[2 * i] = a; ((__half2*)lo)[2 * i + 1] = b2;
}

// ---------------- GEMM 2-pass fp16: cp.async double-buffer + ldmatrix ------
// C[M,N] = (Ah+Al) @ Bth^T + bias.  Block 128x128, BK=32, 2 stages.
#define BKG   32
#define PITCH 40   // halfs per smem row (32 data + 8 pad); 80B — ldmatrix conflict-free

__device__ __forceinline__ void gemm2p_body(
    const h16* __restrict__ Ah, const h16* __restrict__ Al,
    const h16* __restrict__ Bth, const float* __restrict__ bias,
    float* __restrict__ C, int M, int N, int K)
{
    extern __shared__ h16 smp[];
    // layout: sAh[2][128][PITCH] | sAl[2][128][PITCH] | sBh[2][128][PITCH]
    h16* sAh = smp;
    h16* sAl = smp + 2 * 128 * PITCH;
    h16* sBh = smp + 4 * 128 * PITCH;
    const uint32_t stStride = 128 * PITCH * 2;  // bytes per stage

    const int tid  = threadIdx.x;
    const int w    = tid >> 5, lane = tid & 31;
    const int m0   = (w & 1) * 64;
    const int n0   = (w >> 1) * 32;
    const int blkM = blockIdx.y * 128;
    const int blkN = blockIdx.x * 128;

    // cp.async load pattern: each thread 2 chunks of 16B per array per stage
    const int lr = tid >> 2;            // 0..63
    const int lk = (tid & 3) * 8;       // 0,8,16,24
    const h16* gAh = Ah  + (size_t)(blkM + lr) * K + lk;
    const h16* gAl = Al  + (size_t)(blkM + lr) * K + lk;
    const h16* gB  = Bth + (size_t)(blkN + lr) * K + lk;

    const uint32_t dAh0 = smem_u32(sAh) + (lr * PITCH + lk) * 2;
    const uint32_t dAh1 = smem_u32(sAh) + ((lr + 64) * PITCH + lk) * 2;
    const uint32_t dAl0 = smem_u32(sAl) + (lr * PITCH + lk) * 2;
    const uint32_t dAl1 = smem_u32(sAl) + ((lr + 64) * PITCH + lk) * 2;
    const uint32_t dB0  = smem_u32(sBh) + (lr * PITCH + lk) * 2;
    const uint32_t dB1  = smem_u32(sBh) + ((lr + 64) * PITCH + lk) * 2;

    // ldmatrix per-lane offsets (bytes)
    const uint32_t offA = ((lane & 15) * PITCH + (lane >> 4) * 8) * 2;
    const uint32_t offB = ((((lane >> 4) * 8) + (lane & 7)) * PITCH + ((lane >> 3) & 1) * 8) * 2;
    const uint32_t aAh = smem_u32(sAh) + offA;
    const uint32_t aAl = smem_u32(sAl) + offA;
    const uint32_t aB  = smem_u32(sBh) + offB;

    float acc[4][4][4];
#pragma unroll
    for (int i = 0; i < 4; i++)
#pragma unroll
        for (int j = 0; j < 4; j++)
#pragma unroll
            for (int v = 0; v < 4; v++) acc[i][j][v] = 0.f;

    const int niter = K / BKG;

    // prologue: stage 0
    {
        cp16(dAh0, gAh); cp16(dAh1, gAh + (size_t)64 * K);
        cp16(dAl0, gAl); cp16(dAl1, gAl + (size_t)64 * K);
        cp16(dB0,  gB);  cp16(dB1,  gB  + (size_t)64 * K);
        CP_COMMIT();
    }

    for (int it = 0; it < niter; it++) {
        if (it + 1 < niter) {
            const int st = (it + 1) & 1;
            const int k0 = (it + 1) * BKG;
            const uint32_t so = st * stStride;
            cp16(dAh0 + so, gAh + k0); cp16(dAh1 + so, gAh + (size_t)64 * K + k0);
            cp16(dAl0 + so, gAl + k0); cp16(dAl1 + so, gAl + (size_t)64 * K + k0);
            cp16(dB0 + so,  gB + k0);  cp16(dB1 + so,  gB  + (size_t)64 * K + k0);
        }
        CP_COMMIT();
        CP_WAIT1();
        __syncthreads();

        const uint32_t so = (it & 1) * stStride;
#pragma unroll
        for (int kk = 0; kk < BKG; kk += 16) {
            uint32_t ah[4][4], al[4][4], bh[4][2];
#pragma unroll
            for (int mt = 0; mt < 4; mt++) {
                const uint32_t rowoff = ((m0 + mt * 16) * PITCH + kk) * 2;
                ldsm_x4(ah[mt][0], ah[mt][1], ah[mt][2], ah[mt][3], aAh + so + rowoff);
                ldsm_x4(al[mt][0], al[mt][1], al[mt][2], al[mt][3], aAl + so + rowoff);
            }
            ldsm_x4(bh[0][0], bh[0][1], bh[1][0], bh[1][1],
                    aB + so + ((n0)      * PITCH + kk) * 2);
            ldsm_x4(bh[2][0], bh[2][1], bh[3][0], bh[3][1],
                    aB + so + ((n0 + 16) * PITCH + kk) * 2);
#pragma unroll
            for (int mt = 0; mt < 4; mt++)
#pragma unroll
                for (int nt = 0; nt < 4; nt++) {
                    mma_f16(acc[mt][nt], ah[mt][0], ah[mt][1], ah[mt][2], ah[mt][3],
                            bh[nt][0], bh[nt][1]);
                    mma_f16(acc[mt][nt], al[mt][0], al[mt][1], al[mt][2], al[mt][3],
                            bh[nt][0], bh[nt][1]);
                }
        }
        __syncthreads();
    }

    const int lg = lane >> 2, tg = lane & 3;
#pragma unroll
    for (int mt = 0; mt < 4; mt++)
#pragma unroll
        for (int nt = 0; nt < 4; nt++) {
            const int col = blkN + n0 + nt * 8 + 2 * tg;
            const float b0 = bias[col], b1 = bias[col + 1];
            const int r0 = blkM + m0 + mt * 16 + lg;
            float2 o;
            o.x = acc[mt][nt][0] + b0; o.y = acc[mt][nt][1] + b1;
            *(float2*)(C + (size_t)r0 * N + col) = o;
            o.x = acc[mt][nt][2] + b0; o.y = acc[mt][nt][3] + b1;
            *(float2*)(C + (size_t)(r0 + 8) * N + col) = o;
        }
}

__global__ __launch_bounds__(256) void gemm2p(
    const h16* __restrict__ Ah, const h16* __restrict__ Al,
    const h16* __restrict__ Bth, const float* __restrict__ bias,
    float* __restrict__ C, int M, int N, int K)
{
    gemm2p_body(Ah, Al, Bth, bias, C, M, N, K);
}

__global__ __launch_bounds__(256) void gemm2p_kv(
    const h16* __restrict__ Ah, const h16* __restrict__ Al,
    const h16* __restrict__ Wkth, const float* __restrict__ bk, float* __restrict__ Kout,
    const h16* __restrict__ Wvth, const float* __restrict__ bv, float* __restrict__ Vout)
{
    if (blockIdx.z == 0) gemm2p_body(Ah, Al, Wkth, bk, Kout, ROWS, KVW, EE);
    else                 gemm2p_body(Ah, Al, Wvth, bv, Vout, ROWS, KVW, EE);
}

// ---------------- RoPE + split ----------------
__global__ __launch_bounds__(256) void rope_split(
    const float* __restrict__ buf, h16* __restrict__ hi,
    h16* __restrict__ lo, int nheads)
{
    int idx = blockIdx.x * 256 + threadIdx.x;
    int ii  = idx & 31;
    int h   = (idx >> 5) % nheads;
    int row = idx / (32 * nheads);
    int t   = row & (TT - 1);
    float ang = (float)(t + 1) * exp2f((float)ii * (-13.2877123795494f / 32.0f));
    float sn, cs;
    sincosf(ang, &sn, &cs);
    size_t off = (size_t)row * (nheads * 64) + h * 64 + ii;
    float x0 = buf[off], x1 = buf[off + 32];
    float y0 = x0 * cs - x1 * sn;
    float y1 = x1 * cs + x0 * sn;
    h16 h0, l0, h1, l1;
    hsplit(y0, h0, l0);
    hsplit(y1, h1, l1);
    hi[off] = h0; hi[off + 32] = h1;
    lo[off] = l0; lo[off + 32] = l1;
}

// ---------------- scores: S = QK^T / 8, 128x128 tiles (R5 verbatim) -------
__global__ __launch_bounds__(256) void attn_scores_f16(
    const h16* __restrict__ Qh, const h16* __restrict__ Ql,
    const h16* __restrict__ Kh, float* __restrict__ att)
{
    int idx = blockIdx.x;
    int qb = (int)((sqrtf(8.f * idx + 1.f) - 1.f) * 0.5f);
    while ((qb + 1) * (qb + 2) / 2 <= idx) qb++;
    while (qb * (qb + 1) / 2 > idx) qb--;
    const int kb = idx - qb * (qb + 1) / 2;

    const int z   = blockIdx.y;
    const int b   = z >> 4;
    const int g   = (z >> 2) & 3;
    const int hkv = z & 3;
    const int hq  = hkv * GG + g;

    extern __shared__ h16 sm[];
    h16 (*sQh)[72] = (h16(*)[72])sm;
    h16 (*sQl)[72] = (h16(*)[72])(sm + 128 * 72);
    h16 (*sKh)[72] = (h16(*)[72])(sm + 2 * 128 * 72);

    const int tid  = threadIdx.x;
    const int w    = tid >> 5, lane = tid & 31;
    const int lg   = lane >> 2, tg = lane & 3;
    const int m0   = (w & 1) * 64;
    const int n0   = (w >> 1) * 32;

    {
        const int lrow = tid >> 1;
        const int lc   = (tid & 1) * 32;
        const h16* qh = Qh + (size_t)(b * TT + qb * 128 + lrow) * EE + hq * 64 + lc;
        const h16* ql = Ql + (size_t)(b * TT + qb * 128 + lrow) * EE + hq * 64 + lc;
        const h16* kh = Kh + (size_t)(b * TT + kb * 128 + lrow) * KVW + hkv * 64 + lc;
#pragma unroll
        for (int v = 0; v < 4; v++) {
            *(uint4*)&sQh[lrow][lc + v * 8] = *(const uint4*)(qh + v * 8);
            *(uint4*)&sQl[lrow][lc + v * 8] = *(const uint4*)(ql + v * 8);
            *(uint4*)&sKh[lrow][lc + v * 8] = *(const uint4*)(kh + v * 8);
        }
    }
    __syncthreads();

    float acc[4][4][4];
#pragma unroll
    for (int i = 0; i < 4; i++)
#pragma unroll
        for (int j = 0; j < 4; j++)
#pragma unroll
            for (int v = 0; v < 4; v++) acc[i][j][v] = 0.f;

#pragma unroll
    for (int kk = 0; kk < 64; kk += 16) {
        uint32_t ah[4][4], al[4][4], bh[4][2];
#pragma unroll
        for (int mt = 0; mt < 4; mt++) {
            const int r = m0 + mt * 16 + lg;
            ah[mt][0] = *(const uint32_t*)&sQh[r][kk + tg * 2];
            ah[mt][1] = *(const uint32_t*)&sQh[r + 8][kk + tg * 2];
            ah[mt][2] = *(const uint32_t*)&sQh[r][kk + tg * 2 + 8];
            ah[mt][3] = *(const uint32_t*)&sQh[r + 8][kk + tg * 2 + 8];
            al[mt][0] = *(const uint32_t*)&sQl[r][kk + tg * 2];
            al[mt][1] = *(const uint32_t*)&sQl[r + 8][kk + tg * 2];
            al[mt][2] = *(const uint32_t*)&sQl[r][kk + tg * 2 + 8];
            al[mt][3] = *(const uint32_t*)&sQl[r + 8][kk + tg * 2 + 8];
        }
#pragma unroll
        for (int nt = 0; nt < 4; nt++) {
            const int n = n0 + nt * 8 + lg;
            bh[nt][0] = *(const uint32_t*)&sKh[n][kk + tg * 2];
            bh[nt][1] = *(const uint32_t*)&sKh[n][kk + tg * 2 + 8];
        }
#pragma unroll
        for (int mt = 0; mt < 4; mt++)
#pragma unroll
            for (int nt = 0; nt < 4; nt++) {
                mma_f16(acc[mt][nt], ah[mt][0], ah[mt][1], ah[mt][2], ah[mt][3],
                        bh[nt][0], bh[nt][1]);
                mma_f16(acc[mt][nt], al[mt][0], al[mt][1], al[mt][2], al[mt][3],
                        bh[nt][0], bh[nt][1]);
            }
    }

    float* obase = att + ((size_t)z * TT + qb * 128) * TT + kb * 128;
#pragma unroll
    for (int mt = 0; mt < 4; mt++)
#pragma unroll
        for (int nt = 0; nt < 4; nt++) {
            const int col = n0 + nt * 8 + 2 * tg;
            const int r0 = m0 + mt * 16 + lg;
            float2 o;
            o.x = acc[mt][nt][0] * 0.125f; o.y = acc[mt][nt][1] * 0.125f;
            *(float2*)(obase + (size_t)r0 * TT + col) = o;
            o.x = acc[mt][nt][2] * 0.125f; o.y = acc[mt][nt][3] * 0.125f;
            *(float2*)(obase + (size_t)(r0 + 8) * TT + col) = o;
        }
}

// ---------------- softmax (R5 verbatim) ----------------
__device__ __forceinline__ float warpReduceMax(float v)
{
#pragma unroll
    for (int o = 16; o > 0; o >>= 1) v = fmaxf(v, __shfl_xor_sync(0xffffffffu, v, o));
    return v;
}
__device__ __forceinline__ float warpReduceSum(float v)
{
#pragma unroll
    for (int o = 16; o > 0; o >>= 1) v += __shfl_xor_sync(0xffffffffu, v, o);
    return v;
}

__global__ __launch_bounds__(256) void softmax_vec(float* __restrict__ att)
{
    const int q = blockIdx.x;
    const int z = blockIdx.y;
    float* row = att + ((size_t)z * TT + q) * TT;
    const int n = q + 1;
    const int tid = threadIdx.x;
    const int base = tid * 8;
    __shared__ float red[8];

    float4 a = *(float4*)(row + base);
    float4 b2 = *(float4*)(row + base + 4);
    float r[8] = {a.x, a.y, a.z, a.w, b2.x, b2.y, b2.z, b2.w};

    float m = -1e30f;
#pragma unroll
    for (int j = 0; j < 8; j++) {
        if (base + j >= n) r[j] = -1e30f;
        m = fmaxf(m, r[j]);
    }
    m = warpReduceMax(m);
    if ((tid & 31) == 0) red[tid >> 5] = m;
    __syncthreads();
    {
        float v = (tid < 8) ? red[tid] : -1e30f;
        v = warpReduceMax(v);
        if (tid == 0) red[0] = v;
    }
    __syncthreads();
    const float M = red[0];
    __syncthreads();

    float s = 0.f;
#pragma unroll
    for (int j = 0; j < 8; j++) {
        float e = (base + j < n) ? __expf(r[j] - M) : 0.f;
        r[j] = e;
        s += e;
    }
    s = warpReduceSum(s);
    if ((tid & 31) == 0) red[tid >> 5] = s;
    __syncthreads();
    {
        float v = (tid < 8) ? red[tid] : 0.f;
        v = warpReduceSum(v);
        if (tid == 0) red[0] = v;
    }
    __syncthreads();
    const float inv = 1.0f / red[0];

    a.x = r[0] * inv; a.y = r[1] * inv; a.z = r[2] * inv; a.w = r[3] * inv;
    b2.x = r[4] * inv; b2.y = r[5] * inv; b2.z = r[6] * inv; b2.w = r[7] * inv;
    *(float4*)(row + base) = a;
    *(float4*)(row + base + 4) = b2;
}

// ---------------- PV: Y = P @ V (R5 verbatim) ----------------
__global__ __launch_bounds__(256) void attn_pv_f16(
    const float* __restrict__ att, const h16* __restrict__ Vth,
    h16* __restrict__ Yh, h16* __restrict__ Yl)
{
    const int qb = (gridDim.x - 1) - blockIdx.x;
    const int z  = blockIdx.y;
    const int b   = z >> 4;
    const int g   = (z >> 2) & 3;
    const int hkv = z & 3;

    extern __shared__ h16 sm[];
    h16 (*sPh)[72] = (h16(*)[72])sm;
    h16 (*sPl)[72] = (h16(*)[72])(sm + 128 * 72);
    h16 (*sVh)[72] = (h16(*)[72])(sm + 2 * 128 * 72);

    const int tid  = threadIdx.x;
    const int w    = tid >> 5, lane = tid & 31;
    const int lg   = lane >> 2, tg = lane & 3;
    const int m0   = (w & 3) * 32;
    const int n0   = (w >> 2) * 32;

    const int prow = tid >> 1;
    const int pc   = (tid & 1) * 32;
    const int vrow = tid >> 2;
    const int vc   = (tid & 3) * 16;

    float acc[2][4][4];
#pragma unroll
    for (int i = 0; i < 2; i++)
#pragma unroll
        for (int j = 0; j < 4; j++)
#pragma unroll
            for (int v = 0; v < 4; v++) acc[i][j][v] = 0.f;

    const float* attrow = att + ((size_t)z * TT + qb * 128 + prow) * TT + pc;
    const h16* vbh = Vth + (size_t)(b * KVW + hkv * 64 + vrow) * TT + vc;

    const int nkb = 2 * qb + 2;
    for (int kb = 0; kb < nkb; kb++) {
#pragma unroll
        for (int v = 0; v < 8; v++) {
            float4 p = *(const float4*)(attrow + kb * 64 + v * 4);
            h16 h0, l0, h1, l1, h2, l2, h3, l3;
            hsplit(p.x, h0, l0); hsplit(p.y, h1, l1);
            hsplit(p.z, h2, l2); hsplit(p.w, h3, l3);
            __half2 t;
            t.x = h0; t.y = h1; *(__half2*)&sPh[prow][pc + v * 4] = t;
            t.x = h2; t.y = h3; *(__half2*)&sPh[prow][pc + v * 4 + 2] = t;
            t.x = l0; t.y = l1; *(__half2*)&sPl[prow][pc + v * 4] = t;
            t.x = l2; t.y = l3; *(__half2*)&sPl[prow][pc + v * 4 + 2] = t;
        }
        *(uint4*)&sVh[vrow][vc]     = *(const uint4*)(vbh + kb * 64);
        *(uint4*)&sVh[vrow][vc + 8] = *(const uint4*)(vbh + kb * 64 + 8);
        __syncthreads();

#pragma unroll
        for (int kk = 0; kk < 64; kk += 16) {
            uint32_t ah[2][4], al[2][4], bh[4][2];
#pragma unroll
            for (int mt = 0; mt < 2; mt++) {
                const int r = m0 + mt * 16 + lg;
                ah[mt][0] = *(const uint32_t*)&sPh[r][kk + tg * 2];
                ah[mt][1] = *(const uint32_t*)&sPh[r + 8][kk + tg * 2];
                ah[mt][2] = *(const uint32_t*)&sPh[r][kk + tg * 2 + 8];
                ah[mt][3] = *(const uint32_t*)&sPh[r + 8][kk + tg * 2 + 8];
                al[mt][0] = *(const uint32_t*)&sPl[r][kk + tg * 2];
                al[mt][1] = *(const uint32_t*)&sPl[r + 8][kk + tg * 2];
                al[mt][2] = *(const uint32_t*)&sPl[r][kk + tg * 2 + 8];
                al[mt][3] = *(const uint32_t*)&sPl[r + 8][kk + tg * 2 + 8];
            }
#pragma unroll
            for (int nt = 0; nt < 4; nt++) {
                const int n = n0 + nt * 8 + lg;
                bh[nt][0] = *(const uint32_t*)&sVh[n][kk + tg * 2];
                bh[nt][1] = *(const uint32_t*)&sVh[n][kk + tg * 2 + 8];
            }
#pragma unroll
            for (int mt = 0; mt < 2; mt++)
#pragma unroll
                for (int nt = 0; nt < 4; nt++) {
                    mma_f16(acc[mt][nt], ah[mt][0], ah[mt][1], ah[mt][2], ah[mt][3],
                            bh[nt][0], bh[nt][1]);
                    mma_f16(acc[mt][nt], al[mt][0], al[mt][1], al[mt][2], al[mt][3],
                            bh[nt][0], bh[nt][1]);
                }
        }
        __syncthreads();
    }

    const int colbase = hkv * 256 + g * 64;
#pragma unroll
    for (int mt = 0; mt < 2; mt++)
#pragma unroll
        for (int nt = 0; nt < 4; nt++) {
            const int col = colbase + n0 + nt * 8 + 2 * tg;
            const int r0 = b * TT + qb * 128 + m0 + mt * 16 + lg;
            h16 h0, l0, h1, l1;
            __half2 t;
            hsplit(acc[mt][nt][0], h0, l0); hsplit(acc[mt][nt][1], h1, l1);
            t.x = h0; t.y = h1; *(__half2*)&Yh[(size_t)r0 * EE + col] = t;
            t.x = l0; t.y = l1; *(__half2*)&Yl[(size_t)r0 * EE + col] = t;
            hsplit(acc[mt][nt][2], h0, l0); hsplit(acc[mt][nt][3], h1, l1);
            t.x = h0; t.y = h1; *(__half2*)&Yh[(size_t)(r0 + 8) * EE + col] = t;
            t.x = l0; t.y = l1; *(__half2*)&Yl[(size_t)(r0 + 8) * EE + col] = t;
        }
}

// ---------------- launch ----------------
extern "C" void kernel_launch(void* const* d_in, const int* in_sizes, int n_in,
                              void* d_out, int out_size)
{
    const float* x  = (const float*)d_in[0];
    const float* Wq = (const float*)d_in[2];
    const float* bq = (const float*)d_in[3];
    const float* Wk = (const float*)d_in[4];
    const float* bk = (const float*)d_in[5];
    const float* Wv = (const float*)d_in[6];
    const float* bv = (const float*)d_in[7];
    const float* Wo = (const float*)d_in[8];
    const float* bo = (const float*)d_in[9];
    float* out = (float*)d_out;

    float *Qb, *Kb, *Vb, *attScratch;
    h16 *xh, *xl, *Qh, *Ql, *Kh, *Kl, *Vth, *Yh, *Yl;
    h16 *Wqth, *Wkth, *Wvth, *Woth;
    cudaGetSymbolAddress((void**)&Qb, g_Q);
    cudaGetSymbolAddress((void**)&Kb, g_K);
    cudaGetSymbolAddress((void**)&Vb, g_V);
    cudaGetSymbolAddress((void**)&attScratch, g_Att);
    cudaGetSymbolAddress((void**)&xh, g_xh);
    cudaGetSymbolAddress((void**)&xl, g_xl);
    cudaGetSymbolAddress((void**)&Qh, g_Qh);
    cudaGetSymbolAddress((void**)&Ql, g_Ql);
    cudaGetSymbolAddress((void**)&Kh, g_Kh);
    cudaGetSymbolAddress((void**)&Kl, g_Kl);
    cudaGetSymbolAddress((void**)&Vth, g_Vth);
    cudaGetSymbolAddress((void**)&Yh, g_Yh);
    cudaGetSymbolAddress((void**)&Yl, g_Yl);
    cudaGetSymbolAddress((void**)&Wqth, g_Wqth);
    cudaGetSymbolAddress((void**)&Wkth, g_Wkth);
    cudaGetSymbolAddress((void**)&Wvth, g_Wvth);
    cudaGetSymbolAddress((void**)&Woth, g_Woth);

    float* att = ((size_t)out_size >= Y_ELEMS + ATT_ELEMS) ? (out + Y_ELEMS)
                                                           : attScratch;

    const int SMEM_GEMM = 6 * 128 * PITCH * (int)sizeof(h16);       // 61440
    const int SMEM_SC = 3 * 128 * 72 * (int)sizeof(h16);            // 55296
    const int SMEM_PV = (2 * 128 + 64) * 72 * (int)sizeof(h16);     // 46080
    cudaFuncSetAttribute(gemm2p,    cudaFuncAttributeMaxDynamicSharedMemorySize, SMEM_GEMM);
    cudaFuncSetAttribute(gemm2p_kv, cudaFuncAttributeMaxDynamicSharedMemorySize, SMEM_GEMM);
    cudaFuncSetAttribute(attn_scores_f16, cudaFuncAttributeMaxDynamicSharedMemorySize, SMEM_SC);
    cudaFuncSetAttribute(attn_pv_f16,    cudaFuncAttributeMaxDynamicSharedMemorySize, SMEM_PV);

    // 0) preprocessing (fused weight transpose)
    wtrans_all<<<dim3(32, 32, 4), dim3(32, 8)>>>(Wq, Wk, Wv, Wo, Wqth, Wkth, Wvth, Woth);
    split_x<<<(ROWS * EE / 4 + 255) / 256, 256>>>((const float4*)x, xh, xl, ROWS * EE / 4);

    // 1) projections (pipelined GEMMs)
    gemm2p<<<dim3(EE / 128, ROWS / 128), 256, SMEM_GEMM>>>(xh, xl, Wqth, bq, Qb, ROWS, EE, EE);
    gemm2p_kv<<<dim3(KVW / 128, ROWS / 128, 2), 256, SMEM_GEMM>>>(
        xh, xl, Wkth, bk, Kb, Wvth, bv, Vb);

    // 2) RoPE + split; V transpose+convert
    rope_split<<<(ROWS * HQn * 32) / 256, 256>>>(Qb, Qh, Ql, HQn);
    rope_split<<<(ROWS * HKVn * 32) / 256, 256>>>(Kb, Kh, Kl, HKVn);
    vtrans_half<<<dim3(KVW / 32, ROWS / 32), dim3(32, 8)>>>(Vb, Vth);

    // 3) scores
    attn_scores_f16<<<dim3(16 * 17 / 2, BB * HQn), 256, SMEM_SC>>>(Qh, Ql, Kh, att);

    // 4) softmax
    softmax_vec<<<dim3(TT, BB * HQn), 256>>>(att);

    // 5) PV
    attn_pv_f16<<<dim3(TT / 128, BB * HQn), 256, SMEM_PV>>>(att, Vth, Yh, Yl);

    // 6) output projection
    gemm2p<<<dim3(EE / 128, ROWS / 128), 256, SMEM_GEMM>>>(Yh, Yl, Woth, bo, out, ROWS, EE, EE);
}